// round 1
// baseline (speedup 1.0000x reference)
#include <cuda_runtime.h>
#include <math.h>

// Problem constants (fixed by the dataset problem)
#define KTOT 32
#define KIND 16
#define KMLP 16
#define DH   64
#define DISTMAX 1.0f
#define MAXNODES 100001
#define MAXIV 65          // at most DH breakpoints -> DH+1 intervals
#define WARPS 8

// ---------------- device scratch (no allocations allowed) ----------------
__device__ int   g_row_ptr[MAXNODES + 2];
__device__ float g_B[MAXIV + 1];          // interval boundaries
__device__ int   g_niv;                   // number of intervals
__device__ float g_slope[MAXIV * KMLP];
__device__ float g_icept[MAXIV * KMLP];
__device__ float g_ac, g_c1, g_bc;
__device__ int   g_sq;

// ---------------- setup: scalars + piecewise-linear MLP tables ----------------
__global__ void setup_kernel(const float* __restrict__ w1, const float* __restrict__ b1,
                             const float* __restrict__ w2, const float* __restrict__ b2,
                             const float* __restrict__ a,  const float* __restrict__ b) {
    __shared__ float bps[DH];
    __shared__ int   nbp;
    __shared__ float B[MAXIV + 1];
    __shared__ int   niv_s;
    int tid = threadIdx.x;
    if (tid == 0) {
        float ac = fminf(fmaxf(a[0], 0.f), 1.f);
        g_ac = ac;
        g_c1 = 1.f - ac;
        float bc = fabsf(b[0]);
        g_bc = bc;
        g_sq = (bc == 2.0f) ? 1 : 0;
        nbp = 0;
    }
    __syncthreads();
    // collect relu breakpoints strictly inside (0, DISTMAX)
    if (tid < DH) {
        float w = w1[tid], bb = b1[tid];
        if (w != 0.f) {
            float t = -bb / w;
            if (t > 0.f && t < DISTMAX) {
                int i = atomicAdd(&nbp, 1);
                bps[i] = t;
            }
        }
    }
    __syncthreads();
    if (tid == 0) {
        // insertion sort (<=64 elements, one-time)
        for (int i = 1; i < nbp; i++) {
            float v = bps[i]; int j = i - 1;
            while (j >= 0 && bps[j] > v) { bps[j + 1] = bps[j]; j--; }
            bps[j + 1] = v;
        }
        B[0] = 0.f;
        for (int i = 0; i < nbp; i++) B[i + 1] = bps[i];
        B[nbp + 1] = DISTMAX;
        niv_s = nbp + 1;
        g_niv = niv_s;
    }
    __syncthreads();
    int niv = niv_s;
    for (int i = tid; i <= niv; i += blockDim.x) g_B[i] = B[i];
    // exact PWL coefficients per (interval, output column)
    for (int idx = tid; idx < niv * KMLP; idx += blockDim.x) {
        int iv = idx / KMLP, k = idx % KMLP;
        float dm = 0.5f * (B[iv] + B[iv + 1]);   // midpoint -> active set constant on interval
        float sl = 0.f, ic = 0.f;
        for (int h = 0; h < DH; h++) {
            float w = w1[h], bb = b1[h];
            if (w * dm + bb > 0.f) {
                float w2v = w2[h * KMLP + k];
                sl += w * w2v;
                ic += bb * w2v;
            }
        }
        g_slope[idx] = sl;
        g_icept[idx] = ic + b2[k];
    }
}

// ---------------- CSR row pointers via binary search (receivers sorted) -------
__global__ void rowptr_kernel(const int* __restrict__ recv, int n_edges, int n_nodes) {
    int i = blockIdx.x * blockDim.x + threadIdx.x;
    if (i > n_nodes) return;
    int lo = 0, hi = n_edges;
    while (lo < hi) {
        int mid = (lo + hi) >> 1;
        if (recv[mid] < i) lo = mid + 1; else hi = mid;
    }
    g_row_ptr[i] = lo;
}

// ---------------- main fused kernel: one warp per node, lane = feature -------
__global__ void __launch_bounds__(WARPS * 32)
main_kernel(const float* __restrict__ nodes, const float* __restrict__ dist,
            const float* __restrict__ pad,   const int* __restrict__ send,
            const float* __restrict__ wgs,   const float* __restrict__ wgg,
            const float* __restrict__ bgg,   float* __restrict__ out,
            int n_nodes) {
    __shared__ float sB[MAXIV + 1];
    __shared__ float sSl[MAXIV * KMLP], sIc[MAXIV * KMLP];
    __shared__ float sWS[KTOT * KTOT], sWG[KTOT * KTOT], sBg[KTOT];
    __shared__ float sN[WARPS][KTOT], sG[WARPS][KTOT];

    int tid = threadIdx.x;
    int niv = g_niv;
    for (int i = tid; i <= niv; i += blockDim.x) sB[i] = g_B[i];
    for (int i = tid; i < niv * KMLP; i += blockDim.x) { sSl[i] = g_slope[i]; sIc[i] = g_icept[i]; }
    for (int i = tid; i < KTOT * KTOT; i += blockDim.x) { sWS[i] = wgs[i]; sWG[i] = wgg[i]; }
    if (tid < KTOT) sBg[tid] = bgg[tid];
    __syncthreads();

    const float ac = g_ac, c1 = g_c1, bc = g_bc;
    const int sq = g_sq;
    const int w = tid >> 5, lane = tid & 31;

    const float binw = DISTMAX / (float)KIND;
    const float lo_b = (float)lane * binw;       // lanes < 16: indicator bin bounds
    const float hi_b = lo_b + binw;
    const int mk = lane - KIND;                  // lanes >= 16: mlp column

    for (int n = blockIdx.x * WARPS + w; n < n_nodes; n += gridDim.x * WARPS) {
        float nval = nodes[n * KTOT + lane];     // receiver row: one load per node
        float nra  = ac * nval;
        int start = g_row_ptr[n], end = g_row_ptr[n + 1];

        float cnt = 0.f;            // indicator bin count  (lanes < 16)
        float acc = 0.f;            // weighted accumulator (both halves)
        float m = -INFINITY, s = 0.f; // online softmax state (lanes >= 16)

        for (int e = start; e < end; e++) {
            float d   = __ldg(&dist[e]);
            float pd_ = __ldg(&pad[e]);
            int sidx  = __ldg(&send[e]);
            float ns  = __ldg(&nodes[sidx * KTOT + lane]);  // 128B coalesced, L2
            float t   = nra - c1 * ns;
            float pw  = sq ? t * t : powf(fabsf(t), bc);
            float we  = pd_ * pw;
            if (lane < KIND) {
                // heaviside((lo-d)*(d-hi),0) -> strictly inside bin
                if ((lo_b - d) * (d - hi_b) > 0.f) { cnt += 1.f; acc += we; }
            } else {
                // interval lookup (uniform across warp; skipped when niv==1)
                int lo = 0, hi = niv - 1;
                while (lo < hi) {
                    int mid = (lo + hi + 1) >> 1;
                    if (d >= sB[mid]) lo = mid; else hi = mid - 1;
                }
                float v  = fmaf(sSl[lo * KMLP + mk], d, sIc[lo * KMLP + mk]);
                float nm = fmaxf(m, v);
                float sc = __expf(m - nm);
                float p  = __expf(v - nm);
                s   = fmaf(s, sc, p);
                acc = fmaf(acc, sc, p * we);
                m   = nm;
            }
        }

        float g;
        if (lane < KIND) g = acc / (cnt + 1e-5f);
        else             g = (s > 0.f) ? acc / s : 0.f;

        sN[w][lane] = nval;
        sG[w][lane] = g;
        __syncwarp();

        // fused epilogue: out[n, lane] = relu(nodes[n]@WS + g@WG + bg)[lane]
        float o = sBg[lane];
        #pragma unroll
        for (int k = 0; k < KTOT; k++) {
            o = fmaf(sN[w][k], sWS[k * KTOT + lane], o);
            o = fmaf(sG[w][k], sWG[k * KTOT + lane], o);
        }
        out[n * KTOT + lane] = fmaxf(o, 0.f);
        __syncwarp();   // protect sN/sG before next node iteration
    }
}

// ---------------- launch ----------------
extern "C" void kernel_launch(void* const* d_in, const int* in_sizes, int n_in,
                              void* d_out, int out_size) {
    const float* nodes     = (const float*)d_in[0];
    const float* distance  = (const float*)d_in[1];
    const float* padding   = (const float*)d_in[2];
    const int*   receivers = (const int*)d_in[3];
    const int*   senders   = (const int*)d_in[4];
    const float* w1        = (const float*)d_in[5];
    const float* b1        = (const float*)d_in[6];
    const float* w2        = (const float*)d_in[7];
    const float* b2        = (const float*)d_in[8];
    const float* a         = (const float*)d_in[9];
    const float* b         = (const float*)d_in[10];
    const float* wgs       = (const float*)d_in[11];
    const float* wgg       = (const float*)d_in[12];
    const float* bgg       = (const float*)d_in[13];

    int n_nodes = in_sizes[0] / KTOT;
    int n_edges = in_sizes[1];

    setup_kernel<<<1, 256>>>(w1, b1, w2, b2, a, b);
    rowptr_kernel<<<(n_nodes + 1 + 255) / 256, 256>>>(receivers, n_edges, n_nodes);
    main_kernel<<<1184, WARPS * 32>>>(nodes, distance, padding, senders,
                                      wgs, wgg, bgg, (float*)d_out, n_nodes);
}

// round 2
// speedup vs baseline: 1.4288x; 1.4288x over previous
#include <cuda_runtime.h>
#include <math.h>

#define KTOT 32
#define KIND 16
#define KMLP 16
#define DH   64
#define DISTMAX 1.0f
#define MAXNODES 100001
#define MAXIV 65
#define WARPS 8
#define FULLMASK 0xffffffffu

// ---------------- device scratch ----------------
__device__ int   g_row_ptr[MAXNODES + 2];
__device__ float g_B[MAXIV + 1];
__device__ int   g_niv;
__device__ float g_slope[MAXIV * KMLP];
__device__ float g_icept[MAXIV * KMLP];
__device__ float g_ac, g_c1, g_bc;
__device__ int   g_sq;

// ---------------- fused pre-pass: block 0 = setup, all blocks = rowptr -------
__global__ void pre_kernel(const float* __restrict__ w1, const float* __restrict__ b1,
                           const float* __restrict__ w2, const float* __restrict__ b2,
                           const float* __restrict__ a,  const float* __restrict__ b,
                           const int* __restrict__ recv, int n_edges, int n_nodes) {
    // -------- rowptr (all blocks) --------
    int i = blockIdx.x * blockDim.x + threadIdx.x;
    if (i <= n_nodes) {
        int lo = 0, hi = n_edges;
        while (lo < hi) {
            int mid = (lo + hi) >> 1;
            if (recv[mid] < i) lo = mid + 1; else hi = mid;
        }
        g_row_ptr[i] = lo;
    }

    // -------- setup (block 0 only) --------
    if (blockIdx.x != 0) return;
    __shared__ float sw1[DH], sb1[DH], sw2[DH * KMLP], sb2[KMLP];
    __shared__ float bps[DH];
    __shared__ int   nbp;
    __shared__ float B[MAXIV + 1];
    __shared__ int   niv_s;
    int tid = threadIdx.x;

    // stage weights coalesced
    for (int k = tid; k < DH; k += blockDim.x) { sw1[k] = w1[k]; sb1[k] = b1[k]; }
    for (int k = tid; k < DH * KMLP; k += blockDim.x) sw2[k] = w2[k];
    if (tid < KMLP) sb2[tid] = b2[tid];
    if (tid == 0) {
        float ac = fminf(fmaxf(a[0], 0.f), 1.f);
        g_ac = ac; g_c1 = 1.f - ac;
        float bc = fabsf(b[0]);
        g_bc = bc; g_sq = (bc == 2.0f) ? 1 : 0;
        nbp = 0;
    }
    __syncthreads();
    if (tid < DH) {
        float w = sw1[tid], bb = sb1[tid];
        if (w != 0.f) {
            float t = -bb / w;
            if (t > 0.f && t < DISTMAX) { int k = atomicAdd(&nbp, 1); bps[k] = t; }
        }
    }
    __syncthreads();
    if (tid == 0) {
        for (int k = 1; k < nbp; k++) {
            float v = bps[k]; int j = k - 1;
            while (j >= 0 && bps[j] > v) { bps[j + 1] = bps[j]; j--; }
            bps[j + 1] = v;
        }
        B[0] = 0.f;
        for (int k = 0; k < nbp; k++) B[k + 1] = bps[k];
        B[nbp + 1] = DISTMAX;
        niv_s = nbp + 1;
        g_niv = niv_s;
    }
    __syncthreads();
    int niv = niv_s;
    for (int k = tid; k <= niv; k += blockDim.x) g_B[k] = B[k];
    for (int idx = tid; idx < niv * KMLP; idx += blockDim.x) {
        int iv = idx / KMLP, k = idx % KMLP;
        float dm = 0.5f * (B[iv] + B[iv + 1]);
        float sl = 0.f, ic = 0.f;
        for (int h = 0; h < DH; h++) {
            float w = sw1[h], bb = sb1[h];
            if (w * dm + bb > 0.f) {
                float w2v = sw2[h * KMLP + k];
                sl += w * w2v;
                ic += bb * w2v;
            }
        }
        g_slope[idx] = sl;
        g_icept[idx] = ic + sb2[k];
    }
}

// ---------------- main fused kernel: one warp per node, lane = feature -------
__global__ void __launch_bounds__(WARPS * 32)
main_kernel(const float* __restrict__ nodes, const float* __restrict__ dist,
            const float* __restrict__ pad,   const int* __restrict__ send,
            const float* __restrict__ wgs,   const float* __restrict__ wgg,
            const float* __restrict__ bgg,   float* __restrict__ out,
            int n_nodes) {
    __shared__ float sB[MAXIV + 1];
    __shared__ float sSl[MAXIV * KMLP], sIc[MAXIV * KMLP];
    __shared__ float sWS[KTOT * KTOT], sWG[KTOT * KTOT], sBg[KTOT];
    __shared__ float sN[WARPS][KTOT], sG[WARPS][KTOT];

    int tid = threadIdx.x;
    int niv = g_niv;
    for (int i = tid; i <= niv; i += blockDim.x) sB[i] = g_B[i];
    for (int i = tid; i < niv * KMLP; i += blockDim.x) { sSl[i] = g_slope[i]; sIc[i] = g_icept[i]; }
    for (int i = tid; i < KTOT * KTOT; i += blockDim.x) { sWS[i] = wgs[i]; sWG[i] = wgg[i]; }
    if (tid < KTOT) sBg[tid] = bgg[tid];
    __syncthreads();

    const float ac = g_ac, c1 = g_c1, bc = g_bc;
    const int sq = g_sq;
    const int w = tid >> 5, lane = tid & 31;
    const bool is_mlp = lane >= KIND;

    const float binw = DISTMAX / (float)KIND;
    const float lo_b = (float)lane * binw;
    const float hi_b = lo_b + binw;
    const int mk = lane - KIND;

    // single-interval fast path (always taken for this dataset: b1 == 0)
    const bool single = (niv == 1);
    float slc = 0.f, icc = 0.f;
    if (is_mlp) { slc = sSl[mk]; icc = sIc[mk]; }

    int n = blockIdx.x * WARPS + w;
    if (n >= n_nodes) return;

    float nval = nodes[n * KTOT + lane];
    float nra  = ac * nval;
    int start = g_row_ptr[n], end = g_row_ptr[n + 1];

    float cnt = 0.f, acc = 0.f;
    float m = -INFINITY, s = 0.f;

    for (int base = start; base < end; base += 32) {
        int e = base + lane;
        bool vld = e < end;
        float dL = vld ? __ldg(&dist[e]) : 0.f;
        float pL = vld ? __ldg(&pad[e])  : 0.f;
        int   sL = vld ? __ldg(&send[e]) : 0;
        int nb = min(32, end - base);

        int j = 0;
        for (; j + 4 <= nb; j += 4) {
            // gather 4 sender rows first -> MLP=4 on the L2 gather
            int   sid[4]; float dd[4], pp[4], ns[4];
            #pragma unroll
            for (int u = 0; u < 4; u++) {
                sid[u] = __shfl_sync(FULLMASK, sL, j + u);
                dd[u]  = __shfl_sync(FULLMASK, dL, j + u);
                pp[u]  = __shfl_sync(FULLMASK, pL, j + u);
            }
            #pragma unroll
            for (int u = 0; u < 4; u++)
                ns[u] = __ldg(&nodes[sid[u] * KTOT + lane]);
            #pragma unroll
            for (int u = 0; u < 4; u++) {
                float d  = dd[u];
                float t  = nra - c1 * ns[u];
                float pw = sq ? t * t : powf(fabsf(t), bc);
                float we = pp[u] * pw;
                if (!is_mlp) {
                    if ((lo_b - d) * (d - hi_b) > 0.f) { cnt += 1.f; acc += we; }
                } else {
                    float v;
                    if (single) v = fmaf(slc, d, icc);
                    else {
                        int lo = 0, hi = niv - 1;
                        while (lo < hi) {
                            int mid = (lo + hi + 1) >> 1;
                            if (d >= sB[mid]) lo = mid; else hi = mid - 1;
                        }
                        v = fmaf(sSl[lo * KMLP + mk], d, sIc[lo * KMLP + mk]);
                    }
                    float nm = fmaxf(m, v);
                    float sc = __expf(m - nm);
                    float p  = __expf(v - nm);
                    s   = fmaf(s, sc, p);
                    acc = fmaf(acc, sc, p * we);
                    m   = nm;
                }
            }
        }
        for (; j < nb; j++) {
            int   sid = __shfl_sync(FULLMASK, sL, j);
            float d   = __shfl_sync(FULLMASK, dL, j);
            float p_  = __shfl_sync(FULLMASK, pL, j);
            float nsv = __ldg(&nodes[sid * KTOT + lane]);
            float t   = nra - c1 * nsv;
            float pw  = sq ? t * t : powf(fabsf(t), bc);
            float we  = p_ * pw;
            if (!is_mlp) {
                if ((lo_b - d) * (d - hi_b) > 0.f) { cnt += 1.f; acc += we; }
            } else {
                float v;
                if (single) v = fmaf(slc, d, icc);
                else {
                    int lo = 0, hi = niv - 1;
                    while (lo < hi) {
                        int mid = (lo + hi + 1) >> 1;
                        if (d >= sB[mid]) lo = mid; else hi = mid - 1;
                    }
                    v = fmaf(sSl[lo * KMLP + mk], d, sIc[lo * KMLP + mk]);
                }
                float nm = fmaxf(m, v);
                float sc = __expf(m - nm);
                float p  = __expf(v - nm);
                s   = fmaf(s, sc, p);
                acc = fmaf(acc, sc, p * we);
                m   = nm;
            }
        }
    }

    float g;
    if (!is_mlp) g = acc / (cnt + 1e-5f);
    else         g = (s > 0.f) ? acc / s : 0.f;

    sN[w][lane] = nval;
    sG[w][lane] = g;
    __syncwarp();

    float o = sBg[lane];
    #pragma unroll
    for (int k = 0; k < KTOT; k++) {
        o = fmaf(sN[w][k], sWS[k * KTOT + lane], o);
        o = fmaf(sG[w][k], sWG[k * KTOT + lane], o);
    }
    out[n * KTOT + lane] = fmaxf(o, 0.f);
}

// ---------------- launch ----------------
extern "C" void kernel_launch(void* const* d_in, const int* in_sizes, int n_in,
                              void* d_out, int out_size) {
    const float* nodes     = (const float*)d_in[0];
    const float* distance  = (const float*)d_in[1];
    const float* padding   = (const float*)d_in[2];
    const int*   receivers = (const int*)d_in[3];
    const int*   senders   = (const int*)d_in[4];
    const float* w1        = (const float*)d_in[5];
    const float* b1        = (const float*)d_in[6];
    const float* w2        = (const float*)d_in[7];
    const float* b2        = (const float*)d_in[8];
    const float* a         = (const float*)d_in[9];
    const float* b         = (const float*)d_in[10];
    const float* wgs       = (const float*)d_in[11];
    const float* wgg       = (const float*)d_in[12];
    const float* bgg       = (const float*)d_in[13];

    int n_nodes = in_sizes[0] / KTOT;
    int n_edges = in_sizes[1];

    pre_kernel<<<(n_nodes + 1 + 255) / 256, 256>>>(w1, b1, w2, b2, a, b,
                                                   receivers, n_edges, n_nodes);
    int nblocks = (n_nodes + WARPS - 1) / WARPS;
    main_kernel<<<nblocks, WARPS * 32>>>(nodes, distance, padding, senders,
                                         wgs, wgg, bgg, (float*)d_out, n_nodes);
}